// round 2
// baseline (speedup 1.0000x reference)
#include <cuda_runtime.h>
#include <math.h>
#include <stdint.h>

// Problem constants
#define BB   32
#define TY   64
#define TXX  64
#define TTT  64
#define HH   512
#define VSS  32000
#define VTT  32000
#define ROWS 2048          // BB*TY == BB*TTT
#define NCB  250           // 32000 / 128 column blocks

// ---------------- scratch (static device memory; no allocs allowed) --------
__device__ __align__(16) float g_ts[ROWS * HH];          // tanh emission states
__device__ __align__(16) float g_tsn[HH];                // null state
__device__ __align__(16) float g_nullLogits[VSS];
__device__ float g_nullPart[125];
__device__ float g_nullSum;
__device__ __align__(16) float g_partE[NCB * ROWS];      // per-colblock exp-sums (emission)
__device__ __align__(16) float g_partT[NCB * ROWS];      // per-colblock exp-sums (target)
__device__ __align__(16) float g_emGath[ROWS * TXX];     // gathered emission logits
__device__ __align__(16) float g_tgtLogit[ROWS];         // gathered target logits
__device__ unsigned long long g_argmax[ROWS];            // encoded (value, ~idx)

// ---------------- small helpers -------------------------------------------
__device__ __forceinline__ void ffma2(unsigned long long &d,
                                      unsigned long long a,
                                      unsigned long long b) {
    asm("fma.rn.f32x2 %0, %1, %2, %0;" : "+l"(d) : "l"(a), "l"(b));
}
__device__ __forceinline__ unsigned long long pk2(float x) {
    unsigned long long r;
    asm("mov.b64 %0, {%1, %1};" : "=l"(r) : "f"(x));
    return r;
}
__device__ __forceinline__ float2 up2(unsigned long long v) {
    float2 r;
    asm("mov.b64 {%0, %1}, %2;" : "=f"(r.x), "=f"(r.y) : "l"(v));
    return r;
}
__device__ __forceinline__ unsigned long long key64(float x, int col) {
    unsigned u = __float_as_uint(x);
    u = (u & 0x80000000u) ? ~u : (u | 0x80000000u);   // order-preserving map
    return ((unsigned long long)u << 32) | (unsigned)(~(unsigned)col);
}

// ---------------- init: reset argmax accumulators (graph replays!) ---------
__global__ void k_init() {
    int i = blockIdx.x * blockDim.x + threadIdx.x;
    if (i < ROWS) g_argmax[i] = 0ull;
}

// ---------------- null state: tsn = tanh(y_null @ W_em + b_em) -------------
__global__ void k_tsn(const float* __restrict__ yn,
                      const float* __restrict__ W,
                      const float* __restrict__ bias) {
    __shared__ float y[HH];
    int t = threadIdx.x;                 // 512 threads
    y[t] = yn[t];
    __syncthreads();
    float acc = bias[t];
#pragma unroll 8
    for (int k = 0; k < HH; k++) acc += y[k] * W[k * HH + t];
    g_tsn[t] = tanhf(acc);
}

// ---------------- null logits over VS + partial exp-sums -------------------
__global__ void k_null(const float* __restrict__ W,
                       const float* __restrict__ bias) {
    __shared__ float tn[HH];
    __shared__ float red[256];
    int t = threadIdx.x;                 // 256 threads, 125 blocks
    tn[t] = g_tsn[t];
    tn[t + 256] = g_tsn[t + 256];
    __syncthreads();
    int c = blockIdx.x * 256 + t;
    float acc = bias[c];
#pragma unroll 8
    for (int k = 0; k < HH; k++) acc += tn[k] * W[k * VSS + c];
    g_nullLogits[c] = acc;
    red[t] = __expf(acc);
    __syncthreads();
    for (int s = 128; s > 0; s >>= 1) {
        if (t < s) red[t] += red[t + s];
        __syncthreads();
    }
    if (t == 0) g_nullPart[blockIdx.x] = red[0];
}

__global__ void k_nullred() {
    __shared__ float red[128];
    int t = threadIdx.x;
    float s = 0.f;
    for (int i = t; i < 125; i += 128) s += g_nullPart[i];
    red[t] = s;
    __syncthreads();
    for (int st = 64; st > 0; st >>= 1) {
        if (t < st) red[t] += red[t + st];
        __syncthreads();
    }
    if (t == 0) g_nullSum = red[0];
}

// ---------------- fused GEMM ------------------------------------------------
// MODE 0: ts = tanh(y_hidden @ W_em + b_em)           (N = 512,  store g_ts)
// MODE 1: emission: Σexp per row + source gather      (N = 32000)
// MODE 2: target:   Σexp per row + target gather + argmax
// Tile: BM=128, BN=128, BK=16, 256 threads, 8x8 micro (split 4+4 rows/cols),
// inner loop = fma.rn.f32x2.
template <int MODE>
__global__ void __launch_bounds__(256) gemm_fused(
        const float* __restrict__ A, const float* __restrict__ Bmat,
        const float* __restrict__ bias, const int* __restrict__ gidx, int N) {
    __shared__ __align__(16) float As[16][132];
    __shared__ __align__(16) float Bs[16][128];
    __shared__ __align__(16) unsigned long long sred[128 * 16]; // also float view
    __shared__ int sidx[128];

    const int tid = threadIdx.x;
    const int tx = tid & 15, ty = tid >> 4;
    const int c0 = blockIdx.x * 128;
    const int r0 = blockIdx.y * 128;
    const float* Ap = (MODE == 1) ? (const float*)g_ts : A;

    unsigned long long acc[8][4];
#pragma unroll
    for (int i = 0; i < 8; i++)
#pragma unroll
        for (int q = 0; q < 4; q++) acc[i][q] = 0ull;

    // preload first k-tile into registers
    float4 pa[2], pb[2];
    {
        const int kbase = 0;
#pragma unroll
        for (int u = 0; u < 2; u++) {
            int v = tid + u * 256;
            int rr = v >> 2, kk4 = (v & 3) << 2;
            pa[u] = *(const float4*)(Ap + (size_t)(r0 + rr) * HH + kbase + kk4);
            int kb = v >> 5, cv = (v & 31) << 2;
            pb[u] = *(const float4*)(Bmat + (size_t)(kbase + kb) * N + c0 + cv);
        }
    }

    for (int kt = 0; kt < 32; kt++) {
        __syncthreads();          // previous compute done
#pragma unroll
        for (int u = 0; u < 2; u++) {
            int v = tid + u * 256;
            int rr = v >> 2, kk4 = (v & 3) << 2;
            As[kk4 + 0][rr] = pa[u].x;
            As[kk4 + 1][rr] = pa[u].y;
            As[kk4 + 2][rr] = pa[u].z;
            As[kk4 + 3][rr] = pa[u].w;
            int kb = v >> 5, cv = (v & 31) << 2;
            *(float4*)&Bs[kb][cv] = pb[u];
        }
        __syncthreads();          // tiles ready
        if (kt + 1 < 32) {
            const int kbase = (kt + 1) * 16;
#pragma unroll
            for (int u = 0; u < 2; u++) {
                int v = tid + u * 256;
                int rr = v >> 2, kk4 = (v & 3) << 2;
                pa[u] = *(const float4*)(Ap + (size_t)(r0 + rr) * HH + kbase + kk4);
                int kb = v >> 5, cv = (v & 31) << 2;
                pb[u] = *(const float4*)(Bmat + (size_t)(kbase + kb) * N + c0 + cv);
            }
        }
#pragma unroll
        for (int kk = 0; kk < 16; kk++) {
            float4 a0 = *(const float4*)&As[kk][ty * 4];
            float4 a1 = *(const float4*)&As[kk][64 + ty * 4];
            ulonglong2 b0 = *(const ulonglong2*)&Bs[kk][tx * 4];
            ulonglong2 b1 = *(const ulonglong2*)&Bs[kk][64 + tx * 4];
            float av[8] = {a0.x, a0.y, a0.z, a0.w, a1.x, a1.y, a1.z, a1.w};
#pragma unroll
            for (int i = 0; i < 8; i++) {
                unsigned long long ap = pk2(av[i]);
                ffma2(acc[i][0], ap, b0.x);
                ffma2(acc[i][1], ap, b0.y);
                ffma2(acc[i][2], ap, b1.x);
                ffma2(acc[i][3], ap, b1.y);
            }
        }
    }

    // ---- epilogue ----
    if (MODE != 0) {
        if (tid < 128) sidx[tid] = gidx[r0 + tid];   // sources/targets, flat row-indexed
    }

    float logit[8][8];
#pragma unroll
    for (int i = 0; i < 8; i++)
#pragma unroll
        for (int q = 0; q < 4; q++) {
            float2 p = up2(acc[i][q]);
            logit[i][2 * q] = p.x;
            logit[i][2 * q + 1] = p.y;
        }
    float bcol[8];
#pragma unroll
    for (int jj = 0; jj < 8; jj++)
        bcol[jj] = bias[c0 + (jj >> 2) * 64 + tx * 4 + (jj & 3)];
#pragma unroll
    for (int i = 0; i < 8; i++)
#pragma unroll
        for (int jj = 0; jj < 8; jj++) logit[i][jj] += bcol[jj];

    if (MODE == 0) {
#pragma unroll
        for (int i = 0; i < 8; i++) {
            int r = r0 + (i >> 2) * 64 + ty * 4 + (i & 3);
#pragma unroll
            for (int jj = 0; jj < 8; jj++) {
                int c = c0 + (jj >> 2) * 64 + tx * 4 + (jj & 3);
                g_ts[(size_t)r * HH + c] = tanhf(logit[i][jj]);
            }
        }
        return;
    }

    __syncthreads();   // sidx visible

    if (MODE == 1) {
        // gather source columns: rows of group g all lie in batch (r0/64 + g)
#pragma unroll
        for (int g = 0; g < 2; g++) {
            for (int j = 0; j < 64; j++) {
                int c = sidx[g * 64 + j];
                int d = c - c0 - tx * 4;
                if (d >= 0 && d < 4) {
#pragma unroll
                    for (int i2 = 0; i2 < 4; i2++)
                        g_emGath[(r0 + g * 64 + ty * 4 + i2) * 64 + j] =
                            logit[g * 4 + i2][d];
                }
                d -= 64;
                if (d >= 0 && d < 4) {
#pragma unroll
                    for (int i2 = 0; i2 < 4; i2++)
                        g_emGath[(r0 + g * 64 + ty * 4 + i2) * 64 + j] =
                            logit[g * 4 + i2][4 + d];
                }
            }
        }
    } else {
        // gather target logit (one column per row)
#pragma unroll
        for (int i = 0; i < 8; i++) {
            int rl = (i >> 2) * 64 + ty * 4 + (i & 3);
            int c = sidx[rl];
            int d = c - c0 - tx * 4;
            if (d >= 0 && d < 4) g_tgtLogit[r0 + rl] = logit[i][d];
            d -= 64;
            if (d >= 0 && d < 4) g_tgtLogit[r0 + rl] = logit[i][4 + d];
        }
    }

    // per-row exp sums (deterministic: one partial per (colblock,row))
    float* fred = (float*)sred;
#pragma unroll
    for (int i = 0; i < 8; i++) {
        int rl = (i >> 2) * 64 + ty * 4 + (i & 3);
        float s = 0.f;
#pragma unroll
        for (int jj = 0; jj < 8; jj++) s += __expf(logit[i][jj]);
        fred[rl * 16 + tx] = s;
    }
    __syncthreads();
    if (tid < 128) {
        float s = 0.f;
#pragma unroll
        for (int t2 = 0; t2 < 16; t2++) s += fred[tid * 16 + t2];
        if (MODE == 1) g_partE[(size_t)blockIdx.x * ROWS + r0 + tid] = s;
        else           g_partT[(size_t)blockIdx.x * ROWS + r0 + tid] = s;
    }

    if (MODE == 2) {
        __syncthreads();   // fred reads done before reuse as u64
#pragma unroll
        for (int i = 0; i < 8; i++) {
            int rl = (i >> 2) * 64 + ty * 4 + (i & 3);
            unsigned long long m = 0ull;
#pragma unroll
            for (int jj = 0; jj < 8; jj++) {
                int c = c0 + (jj >> 2) * 64 + tx * 4 + (jj & 3);
                unsigned long long k = key64(logit[i][jj], c);
                m = (k > m) ? k : m;
            }
            sred[rl * 16 + tx] = m;
        }
        __syncthreads();
        if (tid < 128) {
            unsigned long long m = 0ull;
#pragma unroll
            for (int t2 = 0; t2 < 16; t2++) {
                unsigned long long k = sred[tid * 16 + t2];
                m = (k > m) ? k : m;
            }
            atomicMax(&g_argmax[r0 + tid], m);
        }
    }
}

// ---------------- pack outputs ---------------------------------------------
__global__ void k_pack(const int* __restrict__ sources,
                       const int* __restrict__ tlen,
                       float* __restrict__ out) {
    int row = blockIdx.x * 128 + threadIdx.x;   // 0..2047
    int b = row >> 6, t = row & 63;
    float sE = 0.f, sT = 0.f;
#pragma unroll 10
    for (int cb = 0; cb < NCB; cb++) {
        sE += g_partE[(size_t)cb * ROWS + row];
        sT += g_partT[(size_t)cb * ROWS + row];
    }
    float invE = 1.f / sE;
    float ns = 1.f / g_nullSum;
    // emission_prob (B, 2*TY, TX): t<64 -> gathered softmax, t>=64 -> null row
    size_t eb = (size_t)b * 8192;
    for (int j = 0; j < 64; j++)
        out[eb + t * 64 + j] = __expf(g_emGath[row * 64 + j]) * invE;
    for (int j = 0; j < 64; j++)
        out[eb + 4096 + t * 64 + j] = __expf(g_nullLogits[sources[b * 64 + j]]) * ns;
    // reconstruction
    float mask = (t < tlen[b]) ? 1.f : 0.f;
    float tl = g_tgtLogit[row];
    out[262144 + row] = mask * (__expf(tl) / sT);
    out[264192 + row] = mask * (tl - logf(sT));
    unsigned low = (unsigned)(g_argmax[row] & 0xFFFFFFFFull);
    out[266240 + row] = (float)(~low);
}

// ---------------- launch -----------------------------------------------------
extern "C" void kernel_launch(void* const* d_in, const int* in_sizes, int n_in,
                              void* d_out, int out_size) {
    const float* y_hidden   = (const float*)d_in[0];
    const float* y_null     = (const float*)d_in[1];
    const float* tgt_state  = (const float*)d_in[2];
    const float* W_em       = (const float*)d_in[3];
    const float* b_em       = (const float*)d_in[4];
    const float* W_sv       = (const float*)d_in[5];
    const float* b_sv       = (const float*)d_in[6];
    const float* W_tv       = (const float*)d_in[7];
    const float* b_tv       = (const float*)d_in[8];
    const int*   sources    = (const int*)d_in[9];
    const int*   targets    = (const int*)d_in[10];
    const int*   tlen       = (const int*)d_in[11];
    float* out = (float*)d_out;

    k_init<<<2, 1024>>>();
    k_tsn<<<1, 512>>>(y_null, W_em, b_em);
    gemm_fused<0><<<dim3(4, 16), 256>>>(y_hidden, W_em, b_em, nullptr, HH);
    k_null<<<125, 256>>>(W_sv, b_sv);
    k_nullred<<<1, 128>>>();
    gemm_fused<1><<<dim3(NCB, 16), 256>>>(nullptr, W_sv, b_sv, sources, VSS);
    gemm_fused<2><<<dim3(NCB, 16), 256>>>(tgt_state, W_tv, b_tv, targets, VTT);
    k_pack<<<16, 128>>>(sources, tlen, out);
}

// round 8
// speedup vs baseline: 1.2734x; 1.2734x over previous
#include <cuda_runtime.h>
#include <cuda_fp16.h>
#include <math.h>
#include <stdint.h>

#define HH    512
#define VSS   32000
#define ROWS  2048
#define NCB   250

typedef unsigned long long u64;
typedef unsigned int u32;

// ---------------- static device scratch ----------------
__device__ __align__(16) float g_ts[ROWS * HH];
__device__ __align__(16) float g_tsn[HH];
__device__ __align__(16) float g_nullLogits[VSS];
__device__ float g_nullPart[125];
__device__ float g_nullSum;
__device__ __align__(16) float g_partE[NCB * ROWS];
__device__ __align__(16) float g_partT[NCB * ROWS];
__device__ __align__(16) float g_emGath[ROWS * 64];
__device__ __align__(16) float g_tgtLogit[ROWS];
__device__ u64 g_argmax[ROWS];

// ---------------- helpers ----------------
__device__ __forceinline__ u64 key64(float x, int col) {
    unsigned u = __float_as_uint(x);
    u = (u & 0x80000000u) ? ~u : (u | 0x80000000u);
    return ((u64)u << 32) | (unsigned)(~(unsigned)col);
}
__device__ __forceinline__ void ffma2(u64& d, u64 a, u64 b) {
    asm("fma.rn.f32x2 %0, %1, %2, %0;" : "+l"(d) : "l"(a), "l"(b));
}
__device__ __forceinline__ u64 pk2(float x) {
    u64 r; asm("mov.b64 %0, {%1, %1};" : "=l"(r) : "f"(x)); return r;
}
__device__ __forceinline__ float2 up2(u64 v) {
    float2 r; asm("mov.b64 {%0, %1}, %2;" : "=f"(r.x), "=f"(r.y) : "l"(v)); return r;
}
__device__ __forceinline__ void hmma(float* d, const u32* a, const u32* b) {
    asm volatile("mma.sync.aligned.m16n8k16.row.col.f32.f16.f16.f32 "
                 "{%0,%1,%2,%3},{%4,%5,%6,%7},{%8,%9},{%0,%1,%2,%3};"
                 : "+f"(d[0]), "+f"(d[1]), "+f"(d[2]), "+f"(d[3])
                 : "r"(a[0]), "r"(a[1]), "r"(a[2]), "r"(a[3]), "r"(b[0]), "r"(b[1]));
}
__device__ __forceinline__ u32 packh2(__half a, __half b) {
    __half2 t = __halves2half2(a, b);
    return *(const u32*)&t;
}

// ================= ROUND-1 PROVEN PATH (emission / output 0) =================
__global__ void k_init() {
    int i = blockIdx.x * blockDim.x + threadIdx.x;
    if (i < ROWS) g_argmax[i] = 0ull;
}

__global__ void k_tsn(const float* __restrict__ yn, const float* __restrict__ W,
                      const float* __restrict__ bias) {
    __shared__ float y[HH];
    int t = threadIdx.x;
    y[t] = yn[t];
    __syncthreads();
    float acc = bias[t];
#pragma unroll 8
    for (int k = 0; k < HH; k++) acc += y[k] * W[k * HH + t];
    g_tsn[t] = tanhf(acc);
}

__global__ void k_null(const float* __restrict__ W, const float* __restrict__ bias) {
    __shared__ float tn[HH];
    __shared__ float red[256];
    int t = threadIdx.x;
    tn[t] = g_tsn[t];
    tn[t + 256] = g_tsn[t + 256];
    __syncthreads();
    int c = blockIdx.x * 256 + t;
    float acc = bias[c];
#pragma unroll 8
    for (int k = 0; k < HH; k++) acc += tn[k] * W[k * VSS + c];
    g_nullLogits[c] = acc;
    red[t] = __expf(acc);
    __syncthreads();
    for (int s = 128; s > 0; s >>= 1) {
        if (t < s) red[t] += red[t + s];
        __syncthreads();
    }
    if (t == 0) g_nullPart[blockIdx.x] = red[0];
}

__global__ void k_nullred() {
    __shared__ float red[128];
    int t = threadIdx.x;
    float s = 0.f;
    for (int i = t; i < 125; i += 128) s += g_nullPart[i];
    red[t] = s;
    __syncthreads();
    for (int st = 64; st > 0; st >>= 1) {
        if (t < st) red[t] += red[t + st];
        __syncthreads();
    }
    if (t == 0) g_nullSum = red[0];
}

// MODE 0: ts = tanh(y@W_em+b). MODE 1: emission Σexp + source gather. (round-1 verbatim)
template <int MODE>
__global__ void __launch_bounds__(256) gemm_fused(
        const float* __restrict__ A, const float* __restrict__ Bmat,
        const float* __restrict__ bias, const int* __restrict__ gidx, int N) {
    __shared__ __align__(16) float As[16][132];
    __shared__ __align__(16) float Bs[16][128];
    __shared__ __align__(16) u64 sred[128 * 16];
    __shared__ int sidx[128];

    const int tid = threadIdx.x;
    const int tx = tid & 15, ty = tid >> 4;
    const int c0 = blockIdx.x * 128;
    const int r0 = blockIdx.y * 128;
    const float* Ap = (MODE == 1) ? (const float*)g_ts : A;

    u64 acc[8][4];
#pragma unroll
    for (int i = 0; i < 8; i++)
#pragma unroll
        for (int q = 0; q < 4; q++) acc[i][q] = 0ull;

    float4 pa[2], pb[2];
    {
#pragma unroll
        for (int u = 0; u < 2; u++) {
            int v = tid + u * 256;
            int rr = v >> 2, kk4 = (v & 3) << 2;
            pa[u] = *(const float4*)(Ap + (size_t)(r0 + rr) * HH + kk4);
            int kb = v >> 5, cv = (v & 31) << 2;
            pb[u] = *(const float4*)(Bmat + (size_t)kb * N + c0 + cv);
        }
    }

    for (int kt = 0; kt < 32; kt++) {
        __syncthreads();
#pragma unroll
        for (int u = 0; u < 2; u++) {
            int v = tid + u * 256;
            int rr = v >> 2, kk4 = (v & 3) << 2;
            As[kk4 + 0][rr] = pa[u].x;
            As[kk4 + 1][rr] = pa[u].y;
            As[kk4 + 2][rr] = pa[u].z;
            As[kk4 + 3][rr] = pa[u].w;
            int kb = v >> 5, cv = (v & 31) << 2;
            *(float4*)&Bs[kb][cv] = pb[u];
        }
        __syncthreads();
        if (kt + 1 < 32) {
            const int kbase = (kt + 1) * 16;
#pragma unroll
            for (int u = 0; u < 2; u++) {
                int v = tid + u * 256;
                int rr = v >> 2, kk4 = (v & 3) << 2;
                pa[u] = *(const float4*)(Ap + (size_t)(r0 + rr) * HH + kbase + kk4);
                int kb = v >> 5, cv = (v & 31) << 2;
                pb[u] = *(const float4*)(Bmat + (size_t)(kbase + kb) * N + c0 + cv);
            }
        }
#pragma unroll
        for (int kk = 0; kk < 16; kk++) {
            float4 a0 = *(const float4*)&As[kk][ty * 4];
            float4 a1 = *(const float4*)&As[kk][64 + ty * 4];
            ulonglong2 b0 = *(const ulonglong2*)&Bs[kk][tx * 4];
            ulonglong2 b1 = *(const ulonglong2*)&Bs[kk][64 + tx * 4];
            float av[8] = {a0.x, a0.y, a0.z, a0.w, a1.x, a1.y, a1.z, a1.w};
#pragma unroll
            for (int i = 0; i < 8; i++) {
                u64 ap = pk2(av[i]);
                ffma2(acc[i][0], ap, b0.x);
                ffma2(acc[i][1], ap, b0.y);
                ffma2(acc[i][2], ap, b1.x);
                ffma2(acc[i][3], ap, b1.y);
            }
        }
    }

    if (MODE != 0) {
        if (tid < 128) sidx[tid] = gidx[r0 + tid];
    }

    float logit[8][8];
#pragma unroll
    for (int i = 0; i < 8; i++)
#pragma unroll
        for (int q = 0; q < 4; q++) {
            float2 p = up2(acc[i][q]);
            logit[i][2 * q] = p.x;
            logit[i][2 * q + 1] = p.y;
        }
    float bcol[8];
#pragma unroll
    for (int jj = 0; jj < 8; jj++)
        bcol[jj] = bias[c0 + (jj >> 2) * 64 + tx * 4 + (jj & 3)];
#pragma unroll
    for (int i = 0; i < 8; i++)
#pragma unroll
        for (int jj = 0; jj < 8; jj++) logit[i][jj] += bcol[jj];

    if (MODE == 0) {
#pragma unroll
        for (int i = 0; i < 8; i++) {
            int r = r0 + (i >> 2) * 64 + ty * 4 + (i & 3);
#pragma unroll
            for (int jj = 0; jj < 8; jj++) {
                int c = c0 + (jj >> 2) * 64 + tx * 4 + (jj & 3);
                g_ts[(size_t)r * HH + c] = tanhf(logit[i][jj]);
            }
        }
        return;
    }

    __syncthreads();

#pragma unroll
    for (int g = 0; g < 2; g++) {
        for (int j = 0; j < 64; j++) {
            int c = sidx[g * 64 + j];
            int d = c - c0 - tx * 4;
            if (d >= 0 && d < 4) {
#pragma unroll
                for (int i2 = 0; i2 < 4; i2++)
                    g_emGath[(r0 + g * 64 + ty * 4 + i2) * 64 + j] =
                        logit[g * 4 + i2][d];
            }
            d -= 64;
            if (d >= 0 && d < 4) {
#pragma unroll
                for (int i2 = 0; i2 < 4; i2++)
                    g_emGath[(r0 + g * 64 + ty * 4 + i2) * 64 + j] =
                        logit[g * 4 + i2][4 + d];
            }
        }
    }

    float* fred = (float*)sred;
#pragma unroll
    for (int i = 0; i < 8; i++) {
        int rl = (i >> 2) * 64 + ty * 4 + (i & 3);
        float s = 0.f;
#pragma unroll
        for (int jj = 0; jj < 8; jj++) s += __expf(logit[i][jj]);
        fred[rl * 16 + tx] = s;
    }
    __syncthreads();
    if (tid < 128) {
        float s = 0.f;
#pragma unroll
        for (int t2 = 0; t2 < 16; t2++) s += fred[tid * 16 + t2];
        g_partE[(size_t)blockIdx.x * ROWS + r0 + tid] = s;
    }
}

// round-1 verbatim pack
__global__ void k_pack(const int* __restrict__ sources, const int* __restrict__ tlen,
                       float* __restrict__ out) {
    int row = blockIdx.x * 128 + threadIdx.x;
    int b = row >> 6, t = row & 63;
    float sE = 0.f, sT = 0.f;
#pragma unroll 10
    for (int cb = 0; cb < NCB; cb++) {
        sE += g_partE[(size_t)cb * ROWS + row];
        sT += g_partT[(size_t)cb * ROWS + row];
    }
    float invE = 1.f / sE;
    float ns = 1.f / g_nullSum;
    size_t eb = (size_t)b * 8192;
    for (int j = 0; j < 64; j++)
        out[eb + t * 64 + j] = __expf(g_emGath[row * 64 + j]) * invE;
    for (int j = 0; j < 64; j++)
        out[eb + 4096 + t * 64 + j] = __expf(g_nullLogits[sources[b * 64 + j]]) * ns;
    float mask = (t < tlen[b]) ? 1.f : 0.f;
    float tl = g_tgtLogit[row];
    out[262144 + row] = mask * (__expf(tl) / sT);
    out[264192 + row] = mask * (tl - logf(sT));
    unsigned low = (unsigned)(g_argmax[row] & 0xFFFFFFFFull);
    out[266240 + row] = (float)(~low);
}

// ======== HMMA TARGET PATH, fp32-direct staging (no prep, no cp.async) ========
// smem: Af[128][40] fp32 (A rows x 32 k), Bf[32][132] fp32 (k x n), per 32-k chunk.
// Fragments built in-loop from fp32 per the PTX m16n8k16 fragment tables.
#define ASTR 40
#define BSTR 132
#define AF(r, c) Afp[(r) * ASTR + (c)]
#define BF(k, n) Bfp[(k) * BSTR + (n)]

__global__ void __launch_bounds__(256) hm_target(const float* __restrict__ Ag,
                                                 const float* __restrict__ Bg,
                                                 const float* __restrict__ bias,
                                                 const int* __restrict__ gidx) {
    extern __shared__ char dsm[];
    __shared__ float s_bias[128];
    __shared__ int   s_idx[128];

    float* Afp = (float*)dsm;                         // 128*40*4 = 20480
    float* Bfp = (float*)(dsm + 20480);               // 32*132*4 = 16896

    const int tid = threadIdx.x;
    const int wid = tid >> 5, lane = tid & 31;
    const int wm = wid & 1, wn = wid >> 1;            // 2 x 4 warp grid
    const int lq = lane >> 2;                         // groupID 0..7
    const int r0 = blockIdx.x * 128;
    const int c0 = blockIdx.y * 128;

    if (tid < 128) {
        s_bias[tid] = bias[c0 + tid];
        s_idx[tid] = gidx[r0 + tid];
    }

    float acc[4][4][4];
#pragma unroll
    for (int a = 0; a < 4; a++)
#pragma unroll
        for (int b = 0; b < 4; b++)
#pragma unroll
            for (int c = 0; c < 4; c++) acc[a][b][c] = 0.f;

    for (int kc = 0; kc < 16; kc++) {
        __syncthreads();          // previous consume done
#pragma unroll
        for (int u = 0; u < 4; u++) {
            int v = tid + u * 256;
            int ar = v >> 3, aq = (v & 7) * 4;
            *(float4*)&AF(ar, aq) =
                *(const float4*)(Ag + (size_t)(r0 + ar) * HH + kc * 32 + aq);
            int bk = v >> 5, bq = (v & 31) * 4;
            *(float4*)&BF(bk, bq) =
                *(const float4*)(Bg + (size_t)(kc * 32 + bk) * VSS + c0 + bq);
        }
        __syncthreads();

#pragma unroll
        for (int kk = 0; kk < 2; kk++) {
            const int kb = kk * 16 + 2 * (lane & 3);
            u32 ah[4][4], al[4][4], bh[4][2], bl[4][2];
#pragma unroll
            for (int mt = 0; mt < 4; mt++) {
                int rA = wm * 64 + mt * 16 + lq;
#pragma unroll
                for (int rr = 0; rr < 4; rr++) {
                    int row = rA + 8 * (rr & 1);
                    int k = kb + 8 * (rr >> 1);
                    float2 x = *(const float2*)&AF(row, k);
                    __half hx = __float2half_rn(x.x), hy = __float2half_rn(x.y);
                    ah[mt][rr] = packh2(hx, hy);
                    al[mt][rr] = packh2(__float2half_rn(x.x - __half2float(hx)),
                                        __float2half_rn(x.y - __half2float(hy)));
                }
            }
#pragma unroll
            for (int nt = 0; nt < 4; nt++) {
                int nB = wn * 32 + nt * 8 + lq;
#pragma unroll
                for (int rr = 0; rr < 2; rr++) {
                    float y0 = BF(kb + 8 * rr, nB);
                    float y1 = BF(kb + 8 * rr + 1, nB);
                    __half h0 = __float2half_rn(y0), h1 = __float2half_rn(y1);
                    bh[nt][rr] = packh2(h0, h1);
                    bl[nt][rr] = packh2(__float2half_rn(y0 - __half2float(h0)),
                                        __float2half_rn(y1 - __half2float(h1)));
                }
            }
#pragma unroll
            for (int mt = 0; mt < 4; mt++)
#pragma unroll
                for (int nt = 0; nt < 4; nt++)
                    hmma(acc[mt][nt], ah[mt], bh[nt]);
#pragma unroll
            for (int mt = 0; mt < 4; mt++)
#pragma unroll
                for (int nt = 0; nt < 4; nt++)
                    hmma(acc[mt][nt], al[mt], bh[nt]);
#pragma unroll
            for (int mt = 0; mt < 4; mt++)
#pragma unroll
                for (int nt = 0; nt < 4; nt++)
                    hmma(acc[mt][nt], ah[mt], bl[nt]);
        }
    }

    // ---- dead-simple epilogue: smem logits + per-row sequential scan ----
    __syncthreads();             // all consumes done; reuse dsm as slog
    float* slog = (float*)dsm;   // [128][132]
#pragma unroll
    for (int mt = 0; mt < 4; mt++)
#pragma unroll
        for (int nt = 0; nt < 4; nt++)
#pragma unroll
            for (int rg = 0; rg < 4; rg++) {
                int col = wn * 32 + nt * 8 + (lane & 3) * 2 + (rg & 1);
                int row = wm * 64 + mt * 16 + (lane >> 2) + 8 * (rg >> 1);
                slog[row * 132 + col] = acc[mt][nt][rg] + s_bias[col];
            }
    __syncthreads();

    if (tid < 128) {
        float esum = 0.f;
        u64 kmax = 0ull;
        const float* rowp = slog + tid * 132;
        for (int c = 0; c < 128; c++) {
            float v = rowp[c];
            esum += __expf(v);
            u64 kk = key64(v, c0 + c);
            if (kk > kmax) kmax = kk;
        }
        g_partT[(size_t)blockIdx.y * ROWS + r0 + tid] = esum;
        atomicMax(&g_argmax[r0 + tid], kmax);
        int c = s_idx[tid] - c0;
        if (c >= 0 && c < 128) g_tgtLogit[r0 + tid] = rowp[c];
    }
}

// ---------------- launch ----------------
extern "C" void kernel_launch(void* const* d_in, const int* in_sizes, int n_in,
                              void* d_out, int out_size) {
    const float* y_hidden  = (const float*)d_in[0];
    const float* y_null    = (const float*)d_in[1];
    const float* tgt_state = (const float*)d_in[2];
    const float* W_em      = (const float*)d_in[3];
    const float* b_em      = (const float*)d_in[4];
    const float* W_sv      = (const float*)d_in[5];
    const float* b_sv      = (const float*)d_in[6];
    const float* W_tv      = (const float*)d_in[7];
    const float* b_tv      = (const float*)d_in[8];
    const int*   sources   = (const int*)d_in[9];
    const int*   targets   = (const int*)d_in[10];
    const int*   tlen      = (const int*)d_in[11];
    float* out = (float*)d_out;

    const int DSMEM = 69632;     // max(Af+Bf = 37376, slog = 67584)
    cudaFuncSetAttribute(hm_target, cudaFuncAttributeMaxDynamicSharedMemorySize, DSMEM);

    k_init<<<2, 1024>>>();
    k_tsn<<<1, 512>>>(y_null, W_em, b_em);
    gemm_fused<0><<<dim3(4, 16), 256>>>(y_hidden, W_em, b_em, nullptr, HH);
    k_null<<<125, 256>>>(W_sv, b_sv);
    k_nullred<<<1, 128>>>();
    gemm_fused<1><<<dim3(NCB, 16), 256>>>(nullptr, W_sv, b_sv, sources, VSS);
    hm_target<<<dim3(16, NCB), 256, DSMEM>>>(tgt_state, W_tv, b_tv, targets);
    k_pack<<<16, 128>>>(sources, tlen, out);
}

// round 9
// speedup vs baseline: 2.1481x; 1.6869x over previous
#include <cuda_runtime.h>
#include <cuda_fp16.h>
#include <math.h>
#include <stdint.h>

#define HH    512
#define VSS   32000
#define ROWS  2048
#define NCB   250
#define AROWS 2176    // 2048 rows + null row (2048) + zero pad to 17*128

typedef unsigned long long u64;
typedef unsigned int u32;

// ---------------- static device scratch ----------------
__device__ __align__(16) float g_Ae[AROWS * HH];   // tanh states + null + pad
__device__ __align__(16) float g_nullLogits[VSS];
__device__ float g_nullPart[NCB];
__device__ float g_nullSum;
__device__ __align__(16) float g_partE[NCB * ROWS];
__device__ __align__(16) float g_partT[NCB * ROWS];
__device__ __align__(16) float g_emGath[ROWS * 64];
__device__ __align__(16) float g_tgtLogit[ROWS];
__device__ u64 g_argmax[ROWS];

// ---------------- helpers ----------------
__device__ __forceinline__ u64 key64(float x, int col) {
    unsigned u = __float_as_uint(x);
    u = (u & 0x80000000u) ? ~u : (u | 0x80000000u);
    return ((u64)u << 32) | (unsigned)(~(unsigned)col);
}
__device__ __forceinline__ void ffma2(u64& d, u64 a, u64 b) {
    asm("fma.rn.f32x2 %0, %1, %2, %0;" : "+l"(d) : "l"(a), "l"(b));
}
__device__ __forceinline__ u64 pk2(float x) {
    u64 r; asm("mov.b64 %0, {%1, %1};" : "=l"(r) : "f"(x)); return r;
}
__device__ __forceinline__ float2 up2(u64 v) {
    float2 r; asm("mov.b64 {%0, %1}, %2;" : "=f"(r.x), "=f"(r.y) : "l"(v)); return r;
}
__device__ __forceinline__ void hmma(float* d, const u32* a, const u32* b) {
    asm volatile("mma.sync.aligned.m16n8k16.row.col.f32.f16.f16.f32 "
                 "{%0,%1,%2,%3},{%4,%5,%6,%7},{%8,%9},{%0,%1,%2,%3};"
                 : "+f"(d[0]), "+f"(d[1]), "+f"(d[2]), "+f"(d[3])
                 : "r"(a[0]), "r"(a[1]), "r"(a[2]), "r"(a[3]), "r"(b[0]), "r"(b[1]));
}
__device__ __forceinline__ u32 packh2(__half a, __half b) {
    __half2 t = __halves2half2(a, b);
    return *(const u32*)&t;
}

// ---------------- init: argmax reset + zero A pad rows ----------------
__global__ void k_init() {
    int i = blockIdx.x * blockDim.x + threadIdx.x;
    if (i < ROWS) g_argmax[i] = 0ull;
    // zero pad rows 2049..2175 (127 rows * 512 = 65024 floats)
    if (i < 127 * HH) g_Ae[(2049) * HH + i] = 0.f;
}

// null state -> row 2048 of g_Ae
__global__ void k_tsn(const float* __restrict__ yn, const float* __restrict__ W,
                      const float* __restrict__ bias) {
    __shared__ float y[HH];
    int t = threadIdx.x;
    y[t] = yn[t];
    __syncthreads();
    float acc = bias[t];
#pragma unroll 8
    for (int k = 0; k < HH; k++) acc += y[k] * W[k * HH + t];
    g_Ae[ROWS * HH + t] = tanhf(acc);
}

// ts = tanh(y_hidden @ W_em + b_em) -> g_Ae rows 0..2047  (round-1 proven FFMA2)
__global__ void __launch_bounds__(256) k_ts(const float* __restrict__ A,
                                            const float* __restrict__ Bmat,
                                            const float* __restrict__ bias) {
    __shared__ __align__(16) float As[16][132];
    __shared__ __align__(16) float Bs[16][128];
    const int tid = threadIdx.x;
    const int tx = tid & 15, ty = tid >> 4;
    const int c0 = blockIdx.x * 128;
    const int r0 = blockIdx.y * 128;

    u64 acc[8][4];
#pragma unroll
    for (int i = 0; i < 8; i++)
#pragma unroll
        for (int q = 0; q < 4; q++) acc[i][q] = 0ull;

    float4 pa[2], pb[2];
#pragma unroll
    for (int u = 0; u < 2; u++) {
        int v = tid + u * 256;
        pa[u] = *(const float4*)(A + (size_t)(r0 + (v >> 2)) * HH + ((v & 3) << 2));
        pb[u] = *(const float4*)(Bmat + (size_t)(v >> 5) * HH + c0 + ((v & 31) << 2));
    }
    for (int kt = 0; kt < 32; kt++) {
        __syncthreads();
#pragma unroll
        for (int u = 0; u < 2; u++) {
            int v = tid + u * 256;
            int rr = v >> 2, k4 = (v & 3) << 2;
            As[k4 + 0][rr] = pa[u].x; As[k4 + 1][rr] = pa[u].y;
            As[k4 + 2][rr] = pa[u].z; As[k4 + 3][rr] = pa[u].w;
            *(float4*)&Bs[v >> 5][(v & 31) << 2] = pb[u];
        }
        __syncthreads();
        if (kt + 1 < 32) {
            int kb = (kt + 1) * 16;
#pragma unroll
            for (int u = 0; u < 2; u++) {
                int v = tid + u * 256;
                pa[u] = *(const float4*)(A + (size_t)(r0 + (v >> 2)) * HH + kb + ((v & 3) << 2));
                pb[u] = *(const float4*)(Bmat + (size_t)(kb + (v >> 5)) * HH + c0 + ((v & 31) << 2));
            }
        }
#pragma unroll
        for (int kk = 0; kk < 16; kk++) {
            float4 a0 = *(const float4*)&As[kk][ty * 4];
            float4 a1 = *(const float4*)&As[kk][64 + ty * 4];
            ulonglong2 b0 = *(const ulonglong2*)&Bs[kk][tx * 4];
            ulonglong2 b1 = *(const ulonglong2*)&Bs[kk][64 + tx * 4];
            float av[8] = {a0.x, a0.y, a0.z, a0.w, a1.x, a1.y, a1.z, a1.w};
#pragma unroll
            for (int i = 0; i < 8; i++) {
                u64 ap = pk2(av[i]);
                ffma2(acc[i][0], ap, b0.x); ffma2(acc[i][1], ap, b0.y);
                ffma2(acc[i][2], ap, b1.x); ffma2(acc[i][3], ap, b1.y);
            }
        }
    }
#pragma unroll
    for (int i = 0; i < 8; i++) {
        int r = r0 + (i >> 2) * 64 + ty * 4 + (i & 3);
#pragma unroll
        for (int q = 0; q < 4; q++) {
            float2 p = up2(acc[i][q]);
            int c = c0 + (q >> 1) * 64 + tx * 4 + (q & 1) * 2;
            g_Ae[(size_t)r * HH + c]     = tanhf(p.x + bias[c]);
            g_Ae[(size_t)r * HH + c + 1] = tanhf(p.y + bias[c + 1]);
        }
    }
}

// ======== HMMA fused GEMM (round-8 proven core + register prefetch) ========
// TMODE 0: emission (A = g_Ae incl null row, grid.x = 17; gather + null epilogue)
// TMODE 1: target   (A = tgt_state, grid.x = 16; argmax + tgt gather epilogue)
#define ASTR 40
#define BSTR 132
#define AF(r, c) Afp[(r) * ASTR + (c)]
#define BF(k, n) Bfp[(k) * BSTR + (n)]

template <int TMODE>
__global__ void __launch_bounds__(256) hm_gemm(const float* __restrict__ Ag,
                                               const float* __restrict__ Bg,
                                               const float* __restrict__ bias,
                                               const int* __restrict__ gidx) {
    extern __shared__ char dsm[];
    __shared__ float s_bias[128];
    __shared__ int   s_idx[128];

    float* Afp = (float*)dsm;                 // 128*40*4 = 20480
    float* Bfp = (float*)(dsm + 20480);       // 32*132*4 = 16896

    const int tid = threadIdx.x;
    const int wid = tid >> 5, lane = tid & 31;
    const int wm = wid & 1, wn = wid >> 1;    // 2 x 4 warp grid
    const int lq = lane >> 2;
    const int r0 = blockIdx.x * 128;
    const int c0 = blockIdx.y * 128;
    const bool nullblk = (TMODE == 0) && (blockIdx.x == 16);

    const float* Ap = (TMODE == 0) ? (const float*)g_Ae : Ag;

    if (tid < 128) {
        s_bias[tid] = bias[c0 + tid];
        if (!nullblk) s_idx[tid] = gidx[r0 + tid];
    }

    float acc[4][4][4];
#pragma unroll
    for (int a = 0; a < 4; a++)
#pragma unroll
        for (int b = 0; b < 4; b++)
#pragma unroll
            for (int c = 0; c < 4; c++) acc[a][b][c] = 0.f;

    float4 pa[4], pb[4];
#define LDGC(kc) do { \
    _Pragma("unroll") for (int u = 0; u < 4; u++) { \
        int v = tid + u * 256; \
        int ar = v >> 3, aq = (v & 7) * 4; \
        pa[u] = *(const float4*)(Ap + (size_t)(r0 + ar) * HH + (kc) * 32 + aq); \
        int bk = v >> 5, bq = (v & 31) * 4; \
        pb[u] = *(const float4*)(Bg + (size_t)((kc) * 32 + bk) * VSS + c0 + bq); \
    } } while (0)

    LDGC(0);
    for (int kc = 0; kc < 16; kc++) {
        __syncthreads();          // previous consume done
#pragma unroll
        for (int u = 0; u < 4; u++) {
            int v = tid + u * 256;
            int ar = v >> 3, aq = (v & 7) * 4;
            *(float4*)&AF(ar, aq) = pa[u];
            int bk = v >> 5, bq = (v & 31) * 4;
            *(float4*)&BF(bk, bq) = pb[u];
        }
        __syncthreads();          // tiles ready
        if (kc + 1 < 16) LDGC(kc + 1);

#pragma unroll
        for (int kk = 0; kk < 2; kk++) {
            const int kb = kk * 16 + 2 * (lane & 3);
            u32 ah[4][4], al[4][4], bh[4][2], bl[4][2];
#pragma unroll
            for (int mt = 0; mt < 4; mt++) {
                int rA = wm * 64 + mt * 16 + lq;
#pragma unroll
                for (int rr = 0; rr < 4; rr++) {
                    int row = rA + 8 * (rr & 1);
                    int k = kb + 8 * (rr >> 1);
                    float2 x = *(const float2*)&AF(row, k);
                    __half hx = __float2half_rn(x.x), hy = __float2half_rn(x.y);
                    ah[mt][rr] = packh2(hx, hy);
                    al[mt][rr] = packh2(__float2half_rn(x.x - __half2float(hx)),
                                        __float2half_rn(x.y - __half2float(hy)));
                }
            }
#pragma unroll
            for (int nt = 0; nt < 4; nt++) {
                int nB = wn * 32 + nt * 8 + lq;
#pragma unroll
                for (int rr = 0; rr < 2; rr++) {
                    float y0 = BF(kb + 8 * rr, nB);
                    float y1 = BF(kb + 8 * rr + 1, nB);
                    __half h0 = __float2half_rn(y0), h1 = __float2half_rn(y1);
                    bh[nt][rr] = packh2(h0, h1);
                    bl[nt][rr] = packh2(__float2half_rn(y0 - __half2float(h0)),
                                        __float2half_rn(y1 - __half2float(h1)));
                }
            }
#pragma unroll
            for (int mt = 0; mt < 4; mt++)
#pragma unroll
                for (int nt = 0; nt < 4; nt++)
                    hmma(acc[mt][nt], ah[mt], bh[nt]);
#pragma unroll
            for (int mt = 0; mt < 4; mt++)
#pragma unroll
                for (int nt = 0; nt < 4; nt++)
                    hmma(acc[mt][nt], al[mt], bh[nt]);
#pragma unroll
            for (int mt = 0; mt < 4; mt++)
#pragma unroll
                for (int nt = 0; nt < 4; nt++)
                    hmma(acc[mt][nt], ah[mt], bl[nt]);
        }
    }
#undef LDGC

    // ---- epilogue: smem logits + per-row sequential scan (round-8 proven) ----
    __syncthreads();             // all smem consumes done; reuse dsm as slog
    float* slog = (float*)dsm;   // [128][132]
#pragma unroll
    for (int mt = 0; mt < 4; mt++)
#pragma unroll
        for (int nt = 0; nt < 4; nt++)
#pragma unroll
            for (int rg = 0; rg < 4; rg++) {
                int col = wn * 32 + nt * 8 + (lane & 3) * 2 + (rg & 1);
                int row = wm * 64 + mt * 16 + (lane >> 2) + 8 * (rg >> 1);
                slog[row * 132 + col] = acc[mt][nt][rg] + s_bias[col];
            }
    __syncthreads();

    if (nullblk) {
        // local row 0 = global row 2048 = null state
        if (tid < 128) g_nullLogits[c0 + tid] = slog[tid];
        if (tid == 0) {
            float esum = 0.f;
            for (int c = 0; c < 128; c++) esum += __expf(slog[c]);
            g_nullPart[blockIdx.y] = esum;
        }
        return;
    }

    if (tid < 128) {
        const float* rowp = slog + tid * 132;
        float esum = 0.f;
        u64 kmax = 0ull;
        for (int c = 0; c < 128; c++) {
            float v = rowp[c];
            esum += __expf(v);
            if (TMODE == 1) {
                u64 kk = key64(v, c0 + c);
                if (kk > kmax) kmax = kk;
            }
        }
        if (TMODE == 0) {
            g_partE[(size_t)blockIdx.y * ROWS + r0 + tid] = esum;
            int g = tid >> 6;
            for (int j = 0; j < 64; j++) {
                int c = s_idx[g * 64 + j] - c0;
                if (c >= 0 && c < 128)
                    g_emGath[(size_t)(r0 + tid) * 64 + j] = rowp[c];
            }
        } else {
            g_partT[(size_t)blockIdx.y * ROWS + r0 + tid] = esum;
            atomicMax(&g_argmax[r0 + tid], kmax);
            int c = s_idx[tid] - c0;
            if (c >= 0 && c < 128) g_tgtLogit[r0 + tid] = rowp[c];
        }
    }
}

// ---------------- null sum reduce + pack ----------------
__global__ void k_nullred() {
    __shared__ float red[128];
    int t = threadIdx.x;
    float s = 0.f;
    for (int i = t; i < NCB; i += 128) s += g_nullPart[i];
    red[t] = s;
    __syncthreads();
    for (int st = 64; st > 0; st >>= 1) {
        if (t < st) red[t] += red[t + st];
        __syncthreads();
    }
    if (t == 0) g_nullSum = red[0];
}

__global__ void k_pack(const int* __restrict__ sources, const int* __restrict__ tlen,
                       float* __restrict__ out) {
    int row = blockIdx.x * 128 + threadIdx.x;
    int b = row >> 6, t = row & 63;
    float sE = 0.f, sT = 0.f;
#pragma unroll 10
    for (int cb = 0; cb < NCB; cb++) {
        sE += g_partE[(size_t)cb * ROWS + row];
        sT += g_partT[(size_t)cb * ROWS + row];
    }
    float invE = 1.f / sE;
    float ns = 1.f / g_nullSum;
    size_t eb = (size_t)b * 8192;
    for (int j = 0; j < 64; j++)
        out[eb + t * 64 + j] = __expf(g_emGath[row * 64 + j]) * invE;
    for (int j = 0; j < 64; j++)
        out[eb + 4096 + t * 64 + j] = __expf(g_nullLogits[sources[b * 64 + j]]) * ns;
    float mask = (t < tlen[b]) ? 1.f : 0.f;
    float tl = g_tgtLogit[row];
    out[262144 + row] = mask * (__expf(tl) / sT);
    out[264192 + row] = mask * (tl - logf(sT));
    unsigned low = (unsigned)(g_argmax[row] & 0xFFFFFFFFull);
    out[266240 + row] = (float)(~low);
}

// ---------------- launch ----------------
extern "C" void kernel_launch(void* const* d_in, const int* in_sizes, int n_in,
                              void* d_out, int out_size) {
    const float* y_hidden  = (const float*)d_in[0];
    const float* y_null    = (const float*)d_in[1];
    const float* tgt_state = (const float*)d_in[2];
    const float* W_em      = (const float*)d_in[3];
    const float* b_em      = (const float*)d_in[4];
    const float* W_sv      = (const float*)d_in[5];
    const float* b_sv      = (const float*)d_in[6];
    const float* W_tv      = (const float*)d_in[7];
    const float* b_tv      = (const float*)d_in[8];
    const int*   sources   = (const int*)d_in[9];
    const int*   targets   = (const int*)d_in[10];
    const int*   tlen      = (const int*)d_in[11];
    float* out = (float*)d_out;

    const int DSMEM = 69632;   // max(Af+Bf = 37376, slog = 67584)
    cudaFuncSetAttribute(hm_gemm<0>, cudaFuncAttributeMaxDynamicSharedMemorySize, DSMEM);
    cudaFuncSetAttribute(hm_gemm<1>, cudaFuncAttributeMaxDynamicSharedMemorySize, DSMEM);

    k_init<<<256, 256>>>();
    k_tsn<<<1, 512>>>(y_null, W_em, b_em);
    k_ts<<<dim3(4, 16), 256>>>(y_hidden, W_em, b_em);
    hm_gemm<0><<<dim3(17, NCB), 256, DSMEM>>>(nullptr, W_sv, b_sv, sources);
    hm_gemm<1><<<dim3(16, NCB), 256, DSMEM>>>(tgt_state, W_tv, b_tv, targets);
    k_nullred<<<1, 128>>>();
    k_pack<<<16, 128>>>(sources, tlen, out);
}

// round 10
// speedup vs baseline: 2.3756x; 1.1059x over previous
#include <cuda_runtime.h>
#include <cuda_fp16.h>
#include <math.h>
#include <stdint.h>

#define HH    512
#define VSS   32000
#define ROWS  2048
#define NCB   250
#define AROWS 2176    // 2048 rows + null row (2048) + zero pad to 17*128

typedef unsigned long long u64;
typedef unsigned int u32;

// ---------------- static device scratch ----------------
__device__ __align__(16) float g_Ae[AROWS * HH];   // tanh states + null + pad
__device__ __align__(16) float g_nullLogits[VSS];
__device__ float g_nullPart[NCB];
__device__ float g_nullSum;
__device__ __align__(16) float g_partE[NCB * ROWS];
__device__ __align__(16) float g_partT[NCB * ROWS];
__device__ __align__(16) float g_emGath[ROWS * 64];
__device__ __align__(16) float g_tgtLogit[ROWS];
__device__ u64 g_argmax[ROWS];

// ---------------- helpers ----------------
__device__ __forceinline__ u64 key64(float x, int col) {
    unsigned u = __float_as_uint(x);
    u = (u & 0x80000000u) ? ~u : (u | 0x80000000u);
    return ((u64)u << 32) | (unsigned)(~(unsigned)col);
}
__device__ __forceinline__ void ffma2(u64& d, u64 a, u64 b) {
    asm("fma.rn.f32x2 %0, %1, %2, %0;" : "+l"(d) : "l"(a), "l"(b));
}
__device__ __forceinline__ u64 pk2(float x) {
    u64 r; asm("mov.b64 %0, {%1, %1};" : "=l"(r) : "f"(x)); return r;
}
__device__ __forceinline__ float2 up2(u64 v) {
    float2 r; asm("mov.b64 {%0, %1}, %2;" : "=f"(r.x), "=f"(r.y) : "l"(v)); return r;
}
__device__ __forceinline__ void hmma(float* d, const u32* a, const u32* b) {
    asm volatile("mma.sync.aligned.m16n8k16.row.col.f32.f16.f16.f32 "
                 "{%0,%1,%2,%3},{%4,%5,%6,%7},{%8,%9},{%0,%1,%2,%3};"
                 : "+f"(d[0]), "+f"(d[1]), "+f"(d[2]), "+f"(d[3])
                 : "r"(a[0]), "r"(a[1]), "r"(a[2]), "r"(a[3]), "r"(b[0]), "r"(b[1]));
}
__device__ __forceinline__ u32 packh2(__half a, __half b) {
    __half2 t = __halves2half2(a, b);
    return *(const u32*)&t;
}
// split two floats into packed hi/lo half2 (low half = first arg)
__device__ __forceinline__ void split2(float x, float y, u32& hi, u32& lo) {
    __half hx = __float2half_rn(x), hy = __float2half_rn(y);
    hi = packh2(hx, hy);
    lo = packh2(__float2half_rn(x - __half2float(hx)),
                __float2half_rn(y - __half2float(hy)));
}

// ---------------- init: argmax reset + zero A pad rows ----------------
__global__ void k_init() {
    int i = blockIdx.x * blockDim.x + threadIdx.x;
    if (i < ROWS) g_argmax[i] = 0ull;
    if (i < 127 * HH) g_Ae[(2049) * HH + i] = 0.f;
}

// null state -> row 2048 of g_Ae
__global__ void k_tsn(const float* __restrict__ yn, const float* __restrict__ W,
                      const float* __restrict__ bias) {
    __shared__ float y[HH];
    int t = threadIdx.x;
    y[t] = yn[t];
    __syncthreads();
    float acc = bias[t];
#pragma unroll 8
    for (int k = 0; k < HH; k++) acc += y[k] * W[k * HH + t];
    g_Ae[ROWS * HH + t] = tanhf(acc);
}

// ts = tanh(y_hidden @ W_em + b_em) -> g_Ae rows 0..2047  (round-1 proven FFMA2)
__global__ void __launch_bounds__(256) k_ts(const float* __restrict__ A,
                                            const float* __restrict__ Bmat,
                                            const float* __restrict__ bias) {
    __shared__ __align__(16) float As[16][132];
    __shared__ __align__(16) float Bs[16][128];
    const int tid = threadIdx.x;
    const int tx = tid & 15, ty = tid >> 4;
    const int c0 = blockIdx.x * 128;
    const int r0 = blockIdx.y * 128;

    u64 acc[8][4];
#pragma unroll
    for (int i = 0; i < 8; i++)
#pragma unroll
        for (int q = 0; q < 4; q++) acc[i][q] = 0ull;

    float4 pa[2], pb[2];
#pragma unroll
    for (int u = 0; u < 2; u++) {
        int v = tid + u * 256;
        pa[u] = *(const float4*)(A + (size_t)(r0 + (v >> 2)) * HH + ((v & 3) << 2));
        pb[u] = *(const float4*)(Bmat + (size_t)(v >> 5) * HH + c0 + ((v & 31) << 2));
    }
    for (int kt = 0; kt < 32; kt++) {
        __syncthreads();
#pragma unroll
        for (int u = 0; u < 2; u++) {
            int v = tid + u * 256;
            int rr = v >> 2, k4 = (v & 3) << 2;
            As[k4 + 0][rr] = pa[u].x; As[k4 + 1][rr] = pa[u].y;
            As[k4 + 2][rr] = pa[u].z; As[k4 + 3][rr] = pa[u].w;
            *(float4*)&Bs[v >> 5][(v & 31) << 2] = pb[u];
        }
        __syncthreads();
        if (kt + 1 < 32) {
            int kb = (kt + 1) * 16;
#pragma unroll
            for (int u = 0; u < 2; u++) {
                int v = tid + u * 256;
                pa[u] = *(const float4*)(A + (size_t)(r0 + (v >> 2)) * HH + kb + ((v & 3) << 2));
                pb[u] = *(const float4*)(Bmat + (size_t)(kb + (v >> 5)) * HH + c0 + ((v & 31) << 2));
            }
        }
#pragma unroll
        for (int kk = 0; kk < 16; kk++) {
            float4 a0 = *(const float4*)&As[kk][ty * 4];
            float4 a1 = *(const float4*)&As[kk][64 + ty * 4];
            ulonglong2 b0 = *(const ulonglong2*)&Bs[kk][tx * 4];
            ulonglong2 b1 = *(const ulonglong2*)&Bs[kk][64 + tx * 4];
            float av[8] = {a0.x, a0.y, a0.z, a0.w, a1.x, a1.y, a1.z, a1.w};
#pragma unroll
            for (int i = 0; i < 8; i++) {
                u64 ap = pk2(av[i]);
                ffma2(acc[i][0], ap, b0.x); ffma2(acc[i][1], ap, b0.y);
                ffma2(acc[i][2], ap, b1.x); ffma2(acc[i][3], ap, b1.y);
            }
        }
    }
#pragma unroll
    for (int i = 0; i < 8; i++) {
        int r = r0 + (i >> 2) * 64 + ty * 4 + (i & 3);
#pragma unroll
        for (int q = 0; q < 4; q++) {
            float2 p = up2(acc[i][q]);
            int c = c0 + (q >> 1) * 64 + tx * 4 + (q & 1) * 2;
            g_Ae[(size_t)r * HH + c]     = tanhf(p.x + bias[c]);
            g_Ae[(size_t)r * HH + c + 1] = tanhf(p.y + bias[c + 1]);
        }
    }
}

// ======== HMMA fused GEMM: staging-time conversion to half planes ========
// smem (u32 units):
//   Ah[128][20] (16 data + 4 pad)   banks (20*lq+m)%32 distinct
//   Al[128][20]
//   Bh[16][136]  (k-pairs x 128 n + 8 pad)  banks (8m+8nt+lq)%32 distinct
//   Bl[16][136]
#define APAD 20
#define BPAD 136

template <int TMODE>
__global__ void __launch_bounds__(256) hm_gemm(const float* __restrict__ Ag,
                                               const float* __restrict__ Bg,
                                               const float* __restrict__ bias,
                                               const int* __restrict__ gidx) {
    extern __shared__ char dsm[];
    __shared__ float s_bias[128];
    __shared__ int   s_idx[128];

    u32* Ah_s = (u32*)dsm;            // 2560 u32
    u32* Al_s = Ah_s + 128 * APAD;    // 2560
    u32* Bh_s = Al_s + 128 * APAD;    // 2176
    u32* Bl_s = Bh_s + 16 * BPAD;     // 2176  (total 37888 B)

    const int tid = threadIdx.x;
    const int wid = tid >> 5, lane = tid & 31;
    const int wm = wid & 1, wn = wid >> 1;    // 2 x 4 warp grid
    const int lq = lane >> 2;                 // groupID 0..7
    const int lm = lane & 3;
    const int r0 = blockIdx.x * 128;
    const int c0 = blockIdx.y * 128;
    const bool nullblk = (TMODE == 0) && (blockIdx.x == 16);

    const float* Ap = (TMODE == 0) ? (const float*)g_Ae : Ag;

    if (tid < 128) {
        s_bias[tid] = bias[c0 + tid];
        if (!nullblk) s_idx[tid] = gidx[r0 + tid];
    }

    float acc[4][4][4];
#pragma unroll
    for (int a = 0; a < 4; a++)
#pragma unroll
        for (int b = 0; b < 4; b++)
#pragma unroll
            for (int c = 0; c < 4; c++) acc[a][b][c] = 0.f;

    float4 pa[4], pb0[2], pb1[2];
#define LDGC(kc) do { \
    _Pragma("unroll") for (int u = 0; u < 4; u++) { \
        int v = tid + u * 256; \
        int ar = v >> 3, aq = (v & 7) * 4; \
        pa[u] = *(const float4*)(Ap + (size_t)(r0 + ar) * HH + (kc) * 32 + aq); \
    } \
    _Pragma("unroll") for (int u = 0; u < 2; u++) { \
        int v = tid + u * 256; \
        int k2 = v >> 5, n4 = (v & 31) * 4; \
        pb0[u] = *(const float4*)(Bg + (size_t)((kc) * 32 + 2 * k2) * VSS + c0 + n4); \
        pb1[u] = *(const float4*)(Bg + (size_t)((kc) * 32 + 2 * k2 + 1) * VSS + c0 + n4); \
    } } while (0)

    LDGC(0);
    for (int kc = 0; kc < 16; kc++) {
        __syncthreads();          // previous consume done
        // --- convert + store half planes ---
#pragma unroll
        for (int u = 0; u < 4; u++) {
            int v = tid + u * 256;
            int ar = v >> 3, q = (v & 7) * 2;        // u32 col base (even)
            u32 h0, l0, h1, l1;
            split2(pa[u].x, pa[u].y, h0, l0);
            split2(pa[u].z, pa[u].w, h1, l1);
            int base = ar * APAD + q;
            Ah_s[base] = h0; Ah_s[base + 1] = h1;
            Al_s[base] = l0; Al_s[base + 1] = l1;
        }
#pragma unroll
        for (int u = 0; u < 2; u++) {
            int v = tid + u * 256;
            int k2 = v >> 5, n4 = (v & 31) * 4;
            int base = k2 * BPAD + n4;
            u32 h, l;
            split2(pb0[u].x, pb1[u].x, h, l); Bh_s[base + 0] = h; Bl_s[base + 0] = l;
            split2(pb0[u].y, pb1[u].y, h, l); Bh_s[base + 1] = h; Bl_s[base + 1] = l;
            split2(pb0[u].z, pb1[u].z, h, l); Bh_s[base + 2] = h; Bl_s[base + 2] = l;
            split2(pb0[u].w, pb1[u].w, h, l); Bh_s[base + 3] = h; Bl_s[base + 3] = l;
        }
        __syncthreads();          // tiles ready
        if (kc + 1 < 16) LDGC(kc + 1);

        // --- pure LDS + HMMA inner loop ---
#pragma unroll
        for (int kk = 0; kk < 2; kk++) {
            u32 ah[4][4], al[4][4], bh[4][2], bl[4][2];
#pragma unroll
            for (int mt = 0; mt < 4; mt++) {
                int rA = wm * 64 + mt * 16 + lq;
#pragma unroll
                for (int rr = 0; rr < 4; rr++) {
                    int row = rA + 8 * (rr & 1);
                    int col = kk * 8 + lm + 4 * (rr >> 1);
                    ah[mt][rr] = Ah_s[row * APAD + col];
                    al[mt][rr] = Al_s[row * APAD + col];
                }
            }
#pragma unroll
            for (int nt = 0; nt < 4; nt++) {
                int nB = wn * 32 + nt * 8 + lq;
#pragma unroll
                for (int rr = 0; rr < 2; rr++) {
                    int p = kk * 8 + lm + 4 * rr;
                    bh[nt][rr] = Bh_s[p * BPAD + nB];
                    bl[nt][rr] = Bl_s[p * BPAD + nB];
                }
            }
#pragma unroll
            for (int mt = 0; mt < 4; mt++)
#pragma unroll
                for (int nt = 0; nt < 4; nt++)
                    hmma(acc[mt][nt], ah[mt], bh[nt]);
#pragma unroll
            for (int mt = 0; mt < 4; mt++)
#pragma unroll
                for (int nt = 0; nt < 4; nt++)
                    hmma(acc[mt][nt], al[mt], bh[nt]);
#pragma unroll
            for (int mt = 0; mt < 4; mt++)
#pragma unroll
                for (int nt = 0; nt < 4; nt++)
                    hmma(acc[mt][nt], ah[mt], bl[nt]);
        }
    }
#undef LDGC

    // ---- epilogue (round-8/9 proven) ----
    __syncthreads();
    float* slog = (float*)dsm;   // [128][132]
#pragma unroll
    for (int mt = 0; mt < 4; mt++)
#pragma unroll
        for (int nt = 0; nt < 4; nt++)
#pragma unroll
            for (int rg = 0; rg < 4; rg++) {
                int col = wn * 32 + nt * 8 + (lane & 3) * 2 + (rg & 1);
                int row = wm * 64 + mt * 16 + (lane >> 2) + 8 * (rg >> 1);
                slog[row * 132 + col] = acc[mt][nt][rg] + s_bias[col];
            }
    __syncthreads();

    if (nullblk) {
        if (tid < 128) g_nullLogits[c0 + tid] = slog[tid];
        if (tid == 0) {
            float esum = 0.f;
            for (int c = 0; c < 128; c++) esum += __expf(slog[c]);
            g_nullPart[blockIdx.y] = esum;
        }
        return;
    }

    if (tid < 128) {
        const float* rowp = slog + tid * 132;
        float esum = 0.f;
        u64 kmax = 0ull;
        for (int c = 0; c < 128; c++) {
            float v = rowp[c];
            esum += __expf(v);
            if (TMODE == 1) {
                u64 kk = key64(v, c0 + c);
                if (kk > kmax) kmax = kk;
            }
        }
        if (TMODE == 0) {
            g_partE[(size_t)blockIdx.y * ROWS + r0 + tid] = esum;
            int g = tid >> 6;
            for (int j = 0; j < 64; j++) {
                int c = s_idx[g * 64 + j] - c0;
                if (c >= 0 && c < 128)
                    g_emGath[(size_t)(r0 + tid) * 64 + j] = rowp[c];
            }
        } else {
            g_partT[(size_t)blockIdx.y * ROWS + r0 + tid] = esum;
            atomicMax(&g_argmax[r0 + tid], kmax);
            int c = s_idx[tid] - c0;
            if (c >= 0 && c < 128) g_tgtLogit[r0 + tid] = rowp[c];
        }
    }
}

// ---------------- null sum reduce + pack ----------------
__global__ void k_nullred() {
    __shared__ float red[128];
    int t = threadIdx.x;
    float s = 0.f;
    for (int i = t; i < NCB; i += 128) s += g_nullPart[i];
    red[t] = s;
    __syncthreads();
    for (int st = 64; st > 0; st >>= 1) {
        if (t < st) red[t] += red[t + st];
        __syncthreads();
    }
    if (t == 0) g_nullSum = red[0];
}

__global__ void k_pack(const int* __restrict__ sources, const int* __restrict__ tlen,
                       float* __restrict__ out) {
    int row = blockIdx.x * 128 + threadIdx.x;
    int b = row >> 6, t = row & 63;
    float sE = 0.f, sT = 0.f;
#pragma unroll 10
    for (int cb = 0; cb < NCB; cb++) {
        sE += g_partE[(size_t)cb * ROWS + row];
        sT += g_partT[(size_t)cb * ROWS + row];
    }
    float invE = 1.f / sE;
    float ns = 1.f / g_nullSum;
    size_t eb = (size_t)b * 8192;
    for (int j = 0; j < 64; j++)
        out[eb + t * 64 + j] = __expf(g_emGath[row * 64 + j]) * invE;
    for (int j = 0; j < 64; j++)
        out[eb + 4096 + t * 64 + j] = __expf(g_nullLogits[sources[b * 64 + j]]) * ns;
    float mask = (t < tlen[b]) ? 1.f : 0.f;
    float tl = g_tgtLogit[row];
    out[262144 + row] = mask * (__expf(tl) / sT);
    out[264192 + row] = mask * (tl - logf(sT));
    unsigned low = (unsigned)(g_argmax[row] & 0xFFFFFFFFull);
    out[266240 + row] = (float)(~low);
}

// ---------------- launch ----------------
extern "C" void kernel_launch(void* const* d_in, const int* in_sizes, int n_in,
                              void* d_out, int out_size) {
    const float* y_hidden  = (const float*)d_in[0];
    const float* y_null    = (const float*)d_in[1];
    const float* tgt_state = (const float*)d_in[2];
    const float* W_em      = (const float*)d_in[3];
    const float* b_em      = (const float*)d_in[4];
    const float* W_sv      = (const float*)d_in[5];
    const float* b_sv      = (const float*)d_in[6];
    const float* W_tv      = (const float*)d_in[7];
    const float* b_tv      = (const float*)d_in[8];
    const int*   sources   = (const int*)d_in[9];
    const int*   targets   = (const int*)d_in[10];
    const int*   tlen      = (const int*)d_in[11];
    float* out = (float*)d_out;

    const int DSMEM = 69632;   // max(planes 37888, slog 67584)
    cudaFuncSetAttribute(hm_gemm<0>, cudaFuncAttributeMaxDynamicSharedMemorySize, DSMEM);
    cudaFuncSetAttribute(hm_gemm<1>, cudaFuncAttributeMaxDynamicSharedMemorySize, DSMEM);

    k_init<<<256, 256>>>();
    k_tsn<<<1, 512>>>(y_null, W_em, b_em);
    k_ts<<<dim3(4, 16), 256>>>(y_hidden, W_em, b_em);
    hm_gemm<0><<<dim3(17, NCB), 256, DSMEM>>>(nullptr, W_sv, b_sv, sources);
    hm_gemm<1><<<dim3(16, NCB), 256, DSMEM>>>(tgt_state, W_tv, b_tv, targets);
    k_nullred<<<1, 128>>>();
    k_pack<<<16, 128>>>(sources, tlen, out);
}